// round 16
// baseline (speedup 1.0000x reference)
#include <cuda_runtime.h>
#include <cuda_fp16.h>
#include <math.h>

#define Nn  100000
#define Ee  1600000
#define Bb  4096
#define FIN 25
#define Hh  128
#define EPSf 1e-5f

// ---------------- scratch (static __device__ — allocation-free) ----------------
__device__ __align__(16) float  g_h [Nn * Hh];   // h2 pre-BN, stored as fp16 (cast)
__device__ __align__(16) __half g_xwh[Nn * Hh];  // h1 fp16, then (in-place) xw2 fp16
__device__ __align__(16) __half g_W2h[Hh * Hh];  // W2 transposed fp16: [n][k]
__device__ int    g_deg[Nn];
__device__ int    g_cursor[Nn];
__device__ float  g_dinv[Nn];
__device__ int    g_rowstart[Nn + 1];
__device__ __align__(8) int2 g_csr[Ee];          // {src, coef as float bits}
__device__ float  g_bnsum[Hh];
__device__ float  g_bnsq [Hh];
__device__ float  g_bnA[Hh];
__device__ float  g_bnB[Hh];
__device__ int    g_bsum[64];
__device__ int    g_bcnt[Bb];
__device__ int    g_boff[Bb];

// runtime-resolved input handles
__device__ int    g_ei64;
__device__ int    g_batch64;
__device__ const float* gp_b[2];
__device__ const float* gp_g[2];
__device__ const float* gp_be[2];

__device__ __forceinline__ int ld_idx(const void* p, long long i, int is64) {
    return is64 ? (int)((const long long*)p)[i] : ((const int*)p)[i];
}

// ---------------- setup: zero scratch + convert W2 to fp16^T ----------------
__global__ void k_setup(const float* __restrict__ W2) {
    int i = blockIdx.x * blockDim.x + threadIdx.x;
    if (i < Nn) { g_deg[i] = 0; g_cursor[i] = 0; }
    if (i < Bb) g_bcnt[i] = 0;
    if (i < Hh) { g_bnsum[i] = 0.f; g_bnsq[i] = 0.f; }
    if (i < Hh * Hh) {              // i = k*128 + n
        int k = i >> 7, n = i & 127;
        g_W2h[n * Hh + k] = __float2half(W2[i]);
    }
}

// ---------------- detect index width + classify 128-vectors ----------------
__global__ void k_classify(const void* ei, const void* batch,
                           const float* c0, const float* c1, const float* c2,
                           const float* c3, const float* c4, const float* c5) {
    int t = threadIdx.x, lane = t & 31, w = t >> 5;
    if (t == 0) {
        const long long* p = (const long long*)ei;
        int ok = 1;
        for (int i = 0; i < 16; i++) { long long v = p[i]; if (v < 0 || v >= Nn) ok = 0; }
        g_ei64 = ok;
        const long long* q = (const long long*)batch;
        int ok2 = 1;
        for (int i = 0; i < 16; i++) { long long v = q[i]; if (v < 0 || v >= Bb) ok2 = 0; }
        g_batch64 = ok2;
    }
    const float* c[6] = {c0, c1, c2, c3, c4, c5};
    __shared__ float s_sum[4], s_abs[4];
    int nb = 0, ng = 0, nbe = 0;
    for (int j = 0; j < 6; j++) {
        float v = c[j][t];
        float s = v, a = fabsf(v);
        for (int o = 16; o > 0; o >>= 1) {
            s += __shfl_down_sync(0xffffffffu, s, o);
            a += __shfl_down_sync(0xffffffffu, a, o);
        }
        if (lane == 0) { s_sum[w] = s; s_abs[w] = a; }
        __syncthreads();
        if (t == 0) {
            float S = s_sum[0] + s_sum[1] + s_sum[2] + s_sum[3];
            float A = s_abs[0] + s_abs[1] + s_abs[2] + s_abs[3];
            if (A == 0.0f)      { if (nb  < 2) gp_b [nb++]  = c[j]; }
            else if (S > 64.0f) { if (ng  < 2) gp_g [ng++]  = c[j]; }
            else                { if (nbe < 2) gp_be[nbe++] = c[j]; }
        }
        __syncthreads();
    }
}

// ---------------- degree histogram + batch count ----------------
__global__ void k_deg(const void* __restrict__ ei, const void* __restrict__ batch) {
    int e = blockIdx.x * blockDim.x + threadIdx.x;
    if (e < Ee) {
        int d = ld_idx(ei, (long long)Ee + e, g_ei64);
        atomicAdd(&g_deg[d], 1);
    }
    if (e < Nn) {
        int b = ld_idx(batch, e, g_batch64);
        atomicAdd(&g_bcnt[b], 1);
    }
}

// ---------------- exclusive scan of deg -> rowstart (+dinv fused) -------------
__global__ void k_scan1() {
    __shared__ int sh[512];
    int b = blockIdx.x, t = threadIdx.x;
    int base = b * 4096 + t * 8;
    int v[8]; int tot = 0;
#pragma unroll
    for (int i = 0; i < 8; i++) {
        int idx = base + i;
        v[i] = (idx < Nn) ? g_deg[idx] : 0;
        if (idx < Nn) g_dinv[idx] = rsqrtf((float)v[i] + 1.0f);
        tot += v[i];
    }
    sh[t] = tot; __syncthreads();
    for (int off = 1; off < 512; off <<= 1) {
        int x = (t >= off) ? sh[t - off] : 0;
        __syncthreads();
        sh[t] += x;
        __syncthreads();
    }
    int run = sh[t] - tot;
#pragma unroll
    for (int i = 0; i < 8; i++) {
        int idx = base + i;
        if (idx < Nn) g_rowstart[idx] = run;
        run += v[i];
    }
    if (t == 511) g_bsum[b] = sh[511];
}

__global__ void k_scan2() {
    int run = 0;
    for (int b = 0; b < 25; b++) { int t = g_bsum[b]; g_bsum[b] = run; run += t; }
    g_rowstart[Nn] = run;
}

__global__ void k_scan3() {
    int i = blockIdx.x * blockDim.x + threadIdx.x;
    if (i < Nn) g_rowstart[i] += g_bsum[i >> 12];
}

__global__ void k_scatter(const void* __restrict__ ei) {
    int e = blockIdx.x * blockDim.x + threadIdx.x;
    if (e >= Ee) return;
    int is64 = g_ei64;
    int s = ld_idx(ei, e, is64);
    int d = ld_idx(ei, (long long)Ee + e, is64);
    int pos = g_rowstart[d] + atomicAdd(&g_cursor[d], 1);
    int2 rec;
    rec.x = s;
    rec.y = __float_as_int(g_dinv[s] * g_dinv[d]);
    g_csr[pos] = rec;
}

// -- layer 1 FUSED: agg(x) + @W1 + b1 -> h1 fp16 (g_xwh) + BN1 stats -----------
// 8 nodes/warp. Gather phase: lane k (<25) accumulates ax_k. Broadcast phase:
// 25 shfl x float4 smem-W1 FMA -> each lane owns channels 4*lane..4*lane+3.
__global__ void __launch_bounds__(256) k_l1(const float* __restrict__ x,
                                            const float* __restrict__ W1) {
    __shared__ float W1s[FIN * Hh];          // [k][n] row-major, 12.8 KB
    __shared__ float s_sum[Hh], s_sq[Hh];
    int t = threadIdx.x, lane = t & 31;
    for (int i = t; i < FIN * Hh; i += 256) W1s[i] = W1[i];
    if (t < Hh) { s_sum[t] = 0.f; s_sq[t] = 0.f; }
    __syncthreads();

    const float* b1 = gp_b[0];
    float4 bv = __ldg(&((const float4*)b1)[lane]);   // channels 4*lane..+3
    bool act = lane < FIN;
    int node0 = ((blockIdx.x * blockDim.x + t) >> 5) * 8;
    float ls0 = 0.f, ls1 = 0.f, ls2 = 0.f, ls3 = 0.f;
    float lq0 = 0.f, lq1 = 0.f, lq2 = 0.f, lq3 = 0.f;

    for (int ni = 0; ni < 8; ni++) {
        int node = node0 + ni;
        if (node >= Nn) break;
        int s = g_rowstart[node];
        int e = g_rowstart[node + 1];
        float acc = 0.f;
        int p = s;
        for (; p + 4 <= e; p += 4) {
            int2 r0 = g_csr[p],     r1 = g_csr[p + 1];
            int2 r2 = g_csr[p + 2], r3 = g_csr[p + 3];
            float v0 = act ? __ldg(&x[r0.x * FIN + lane]) : 0.f;
            float v1 = act ? __ldg(&x[r1.x * FIN + lane]) : 0.f;
            float v2 = act ? __ldg(&x[r2.x * FIN + lane]) : 0.f;
            float v3 = act ? __ldg(&x[r3.x * FIN + lane]) : 0.f;
            acc = fmaf(v0, __int_as_float(r0.y), acc);
            acc = fmaf(v1, __int_as_float(r1.y), acc);
            acc = fmaf(v2, __int_as_float(r2.y), acc);
            acc = fmaf(v3, __int_as_float(r3.y), acc);
        }
        for (; p < e; p++) {
            int2 r0 = g_csr[p];
            float v0 = act ? __ldg(&x[r0.x * FIN + lane]) : 0.f;
            acc = fmaf(v0, __int_as_float(r0.y), acc);
        }
        float dd = g_dinv[node];
        float v  = act ? __ldg(&x[node * FIN + lane]) : 0.f;
        acc = fmaf(v, dd * dd, acc);

        // broadcast ax_k, multiply into 4 owned channels
        float4 o = bv;
#pragma unroll
        for (int k = 0; k < FIN; k++) {
            float a = __shfl_sync(0xffffffffu, acc, k);
            float4 w = *(const float4*)&W1s[k * Hh + lane * 4];
            o.x = fmaf(a, w.x, o.x);
            o.y = fmaf(a, w.y, o.y);
            o.z = fmaf(a, w.z, o.z);
            o.w = fmaf(a, w.w, o.w);
        }
        // store fp16 (8B coalesced per lane)
        __half2 h0 = __floats2half2_rn(o.x, o.y);
        __half2 h1 = __floats2half2_rn(o.z, o.w);
        uint2 pk;
        pk.x = *(const unsigned*)&h0;
        pk.y = *(const unsigned*)&h1;
        *(uint2*)&g_xwh[node * Hh + lane * 4] = pk;
        // exact fp32 stats
        ls0 += o.x; lq0 = fmaf(o.x, o.x, lq0);
        ls1 += o.y; lq1 = fmaf(o.y, o.y, lq1);
        ls2 += o.z; lq2 = fmaf(o.z, o.z, lq2);
        ls3 += o.w; lq3 = fmaf(o.w, o.w, lq3);
    }
    atomicAdd(&s_sum[lane * 4 + 0], ls0); atomicAdd(&s_sq[lane * 4 + 0], lq0);
    atomicAdd(&s_sum[lane * 4 + 1], ls1); atomicAdd(&s_sq[lane * 4 + 1], lq1);
    atomicAdd(&s_sum[lane * 4 + 2], ls2); atomicAdd(&s_sq[lane * 4 + 2], lq2);
    atomicAdd(&s_sum[lane * 4 + 3], ls3); atomicAdd(&s_sq[lane * 4 + 3], lq3);
    __syncthreads();
    if (t < Hh) {
        atomicAdd(&g_bnsum[t], s_sum[t]);
        atomicAdd(&g_bnsq [t], s_sq[t]);
    }
}

__global__ void k_bncoef(int layer) {
    int c = threadIdx.x;
    const float* gam = gp_g[layer];
    const float* bet = gp_be[layer];
    double m   = (double)g_bnsum[c] / (double)Nn;
    double var = (double)g_bnsq[c] / (double)Nn - m * m;
    float  A   = (float)((double)gam[c] / sqrt(var + (double)EPSf));
    g_bnA[c] = A;
    g_bnB[c] = bet[c] - (float)m * A;
    g_bnsum[c] = 0.f; g_bnsq[c] = 0.f;   // reset for layer-2 stats
}

// -- GEMM2 (HMMA): relu(bn(h1_fp16)) @ W2 -> xw2 fp16 IN-PLACE into g_xwh ------
__global__ void __launch_bounds__(256) k_gemm2h() {
    __shared__ __half As[128][72];     // pitch 72 halves = 144B (16*9, uint4-safe)
    __shared__ __half Bs[128][72];
    __shared__ float  sA[Hh], sB[Hh];
    int t    = threadIdx.x;            // 256
    int warp = t >> 5, lane = t & 31;
    int grp  = lane >> 2, thr = lane & 3;
    int row0 = blockIdx.x * 128;
    if (t < 128) { sA[t] = g_bnA[t]; sB[t] = g_bnB[t]; }
    __syncthreads();

    float acc[16][4];
#pragma unroll
    for (int n = 0; n < 16; n++)
#pragma unroll
        for (int j = 0; j < 4; j++) acc[n][j] = 0.f;

    for (int ko = 0; ko < Hh; ko += 64) {
        {   // A: 128 rows x 64 k, fp16 load + BN + ReLU + re-round
            int r  = t >> 1;
            int c0 = (t & 1) * 32;
            int row = row0 + r;
#pragma unroll
            for (int j = 0; j < 8; j++) {
                int col = ko + c0 + j * 4;
                float2 f0 = make_float2(0.f, 0.f), f1 = make_float2(0.f, 0.f);
                if (row < Nn) {
                    uint2 raw = *(const uint2*)&g_xwh[row * Hh + col];
                    f0 = __half22float2(*(const __half2*)&raw.x);
                    f1 = __half22float2(*(const __half2*)&raw.y);
                    f0.x = fmaxf(fmaf(f0.x, sA[col + 0], sB[col + 0]), 0.f);
                    f0.y = fmaxf(fmaf(f0.y, sA[col + 1], sB[col + 1]), 0.f);
                    f1.x = fmaxf(fmaf(f1.x, sA[col + 2], sB[col + 2]), 0.f);
                    f1.y = fmaxf(fmaf(f1.y, sA[col + 3], sB[col + 3]), 0.f);
                }
                *(__half2*)&As[r][c0 + j * 4]     = __floats2half2_rn(f0.x, f0.y);
                *(__half2*)&As[r][c0 + j * 4 + 2] = __floats2half2_rn(f1.x, f1.y);
            }
        }
        {   // B: 128 n x 64 k
            int n  = t >> 1;
            int c0 = (t & 1) * 32;
#pragma unroll
            for (int j = 0; j < 4; j++) {
                uint4 w = *(const uint4*)&g_W2h[n * Hh + ko + c0 + j * 8];
                *(uint4*)&Bs[n][c0 + j * 8] = w;
            }
        }
        __syncthreads();
#pragma unroll
        for (int kc = 0; kc < 4; kc++) {
            int kb = kc * 16;
            unsigned a0 = *(const unsigned*)&As[warp * 16 + grp    ][kb + thr * 2];
            unsigned a1 = *(const unsigned*)&As[warp * 16 + grp + 8][kb + thr * 2];
            unsigned a2 = *(const unsigned*)&As[warp * 16 + grp    ][kb + thr * 2 + 8];
            unsigned a3 = *(const unsigned*)&As[warp * 16 + grp + 8][kb + thr * 2 + 8];
#pragma unroll
            for (int n = 0; n < 16; n++) {
                unsigned b0 = *(const unsigned*)&Bs[n * 8 + grp][kb + thr * 2];
                unsigned b1 = *(const unsigned*)&Bs[n * 8 + grp][kb + thr * 2 + 8];
                asm volatile(
                    "mma.sync.aligned.m16n8k16.row.col.f32.f16.f16.f32 "
                    "{%0,%1,%2,%3}, {%4,%5,%6,%7}, {%8,%9}, {%0,%1,%2,%3};"
                    : "+f"(acc[n][0]), "+f"(acc[n][1]), "+f"(acc[n][2]), "+f"(acc[n][3])
                    : "r"(a0), "r"(a1), "r"(a2), "r"(a3), "r"(b0), "r"(b1));
            }
        }
        __syncthreads();
    }
    int rA = row0 + warp * 16 + grp;
    int rB = rA + 8;
#pragma unroll
    for (int n = 0; n < 16; n++) {
        int col = n * 8 + thr * 2;
        if (rA < Nn) *(__half2*)&g_xwh[rA * Hh + col] = __floats2half2_rn(acc[n][0], acc[n][1]);
        if (rB < Nn) *(__half2*)&g_xwh[rB * Hh + col] = __floats2half2_rn(acc[n][2], acc[n][3]);
    }
}

// -- layer-2 aggregation: 8 nodes/warp, fused BN2 stats, h2 stored fp16 --------
__global__ void __launch_bounds__(256) k_agg2h() {
    __shared__ float s_sum[Hh], s_sq[Hh];
    int t = threadIdx.x;
    if (t < Hh) { s_sum[t] = 0.f; s_sq[t] = 0.f; }
    __syncthreads();
    int lane = t & 31;
    int node0 = ((blockIdx.x * blockDim.x + t) >> 5) * 8;
    const float* bias = gp_b[1];
    float4 bv = __ldg(&((const float4*)bias)[lane]);
    const uint2* xw2 = (const uint2*)g_xwh;
    __half* h2 = (__half*)g_h;
    float ls0 = 0.f, ls1 = 0.f, ls2 = 0.f, ls3 = 0.f;
    float lq0 = 0.f, lq1 = 0.f, lq2 = 0.f, lq3 = 0.f;

    for (int ni = 0; ni < 8; ni++) {
        int node = node0 + ni;
        if (node >= Nn) break;
        int s = g_rowstart[node];
        int e = g_rowstart[node + 1];
        float4 acc = make_float4(0.f, 0.f, 0.f, 0.f);
        int p = s;
        for (; p + 4 <= e; p += 4) {
            int2 r0 = g_csr[p],     r1 = g_csr[p + 1];
            int2 r2 = g_csr[p + 2], r3 = g_csr[p + 3];
            uint2 w0 = __ldg(&xw2[r0.x * 32 + lane]);
            uint2 w1 = __ldg(&xw2[r1.x * 32 + lane]);
            uint2 w2 = __ldg(&xw2[r2.x * 32 + lane]);
            uint2 w3 = __ldg(&xw2[r3.x * 32 + lane]);
            float c0 = __int_as_float(r0.y), c1 = __int_as_float(r1.y);
            float c2 = __int_as_float(r2.y), c3 = __int_as_float(r3.y);
            float2 p0, p1;
            p0 = __half22float2(*(const __half2*)&w0.x); p1 = __half22float2(*(const __half2*)&w0.y);
            acc.x = fmaf(p0.x, c0, acc.x); acc.y = fmaf(p0.y, c0, acc.y);
            acc.z = fmaf(p1.x, c0, acc.z); acc.w = fmaf(p1.y, c0, acc.w);
            p0 = __half22float2(*(const __half2*)&w1.x); p1 = __half22float2(*(const __half2*)&w1.y);
            acc.x = fmaf(p0.x, c1, acc.x); acc.y = fmaf(p0.y, c1, acc.y);
            acc.z = fmaf(p1.x, c1, acc.z); acc.w = fmaf(p1.y, c1, acc.w);
            p0 = __half22float2(*(const __half2*)&w2.x); p1 = __half22float2(*(const __half2*)&w2.y);
            acc.x = fmaf(p0.x, c2, acc.x); acc.y = fmaf(p0.y, c2, acc.y);
            acc.z = fmaf(p1.x, c2, acc.z); acc.w = fmaf(p1.y, c2, acc.w);
            p0 = __half22float2(*(const __half2*)&w3.x); p1 = __half22float2(*(const __half2*)&w3.y);
            acc.x = fmaf(p0.x, c3, acc.x); acc.y = fmaf(p0.y, c3, acc.y);
            acc.z = fmaf(p1.x, c3, acc.z); acc.w = fmaf(p1.y, c3, acc.w);
        }
        for (; p < e; p++) {
            int2 r0 = g_csr[p];
            uint2 w0 = __ldg(&xw2[r0.x * 32 + lane]);
            float c0 = __int_as_float(r0.y);
            float2 p0 = __half22float2(*(const __half2*)&w0.x);
            float2 p1 = __half22float2(*(const __half2*)&w0.y);
            acc.x = fmaf(p0.x, c0, acc.x); acc.y = fmaf(p0.y, c0, acc.y);
            acc.z = fmaf(p1.x, c0, acc.z); acc.w = fmaf(p1.y, c0, acc.w);
        }
        float dd = g_dinv[node];
        float sc = dd * dd;
        uint2 wr = xw2[node * 32 + lane];
        float2 f0 = __half22float2(*(const __half2*)&wr.x);
        float2 f1 = __half22float2(*(const __half2*)&wr.y);
        acc.x = fmaf(f0.x, sc, acc.x) + bv.x;
        acc.y = fmaf(f0.y, sc, acc.y) + bv.y;
        acc.z = fmaf(f1.x, sc, acc.z) + bv.z;
        acc.w = fmaf(f1.y, sc, acc.w) + bv.w;
        // store h2 as fp16 (stats below stay exact fp32)
        __half2 o0 = __floats2half2_rn(acc.x, acc.y);
        __half2 o1 = __floats2half2_rn(acc.z, acc.w);
        uint2 pk;
        pk.x = *(const unsigned*)&o0;
        pk.y = *(const unsigned*)&o1;
        *(uint2*)&h2[node * Hh + lane * 4] = pk;
        ls0 += acc.x; lq0 = fmaf(acc.x, acc.x, lq0);
        ls1 += acc.y; lq1 = fmaf(acc.y, acc.y, lq1);
        ls2 += acc.z; lq2 = fmaf(acc.z, acc.z, lq2);
        ls3 += acc.w; lq3 = fmaf(acc.w, acc.w, lq3);
    }
    atomicAdd(&s_sum[lane * 4 + 0], ls0); atomicAdd(&s_sq[lane * 4 + 0], lq0);
    atomicAdd(&s_sum[lane * 4 + 1], ls1); atomicAdd(&s_sq[lane * 4 + 1], lq1);
    atomicAdd(&s_sum[lane * 4 + 2], ls2); atomicAdd(&s_sq[lane * 4 + 2], lq2);
    atomicAdd(&s_sum[lane * 4 + 3], ls3); atomicAdd(&s_sq[lane * 4 + 3], lq3);
    __syncthreads();
    if (t < Hh) {
        atomicAdd(&g_bnsum[t], s_sum[t]);
        atomicAdd(&g_bnsq [t], s_sq[t]);
    }
}

// ---------------- batch pooling ----------------
__global__ void k_bscan() {
    __shared__ int sh[1024];
    int t = threadIdx.x;
    int base = t * 4;
    int v[4]; int tot = 0;
#pragma unroll
    for (int i = 0; i < 4; i++) { v[i] = g_bcnt[base + i]; tot += v[i]; }
    sh[t] = tot; __syncthreads();
    for (int off = 1; off < 1024; off <<= 1) {
        int x = (t >= off) ? sh[t - off] : 0;
        __syncthreads();
        sh[t] += x;
        __syncthreads();
    }
    int run = sh[t] - tot;
#pragma unroll
    for (int i = 0; i < 4; i++) { g_boff[base + i] = run; run += v[i]; }
}

__global__ void k_pool(float* __restrict__ out) {
    int g = blockIdx.x;
    int c = threadIdx.x;
    int st = g_boff[g], cn = g_bcnt[g];
    const __half* h2 = (const __half*)g_h;
    float A = g_bnA[c], Bc = g_bnB[c];
    float s = 0.f, mx = -INFINITY;
    for (int r = st; r < st + cn; r++) {
        float v = __half2float(h2[r * Hh + c]);
        v = fmaxf(fmaf(v, A, Bc), 0.f);
        s += v;
        mx = fmaxf(mx, v);
    }
    out[g * 384 + c]       = s / (float)max(cn, 1);
    out[g * 384 + 128 + c] = (cn > 0) ? mx : 0.f;
    out[g * 384 + 256 + c] = s;
}

// ---------------- launch ----------------
extern "C" void kernel_launch(void* const* d_in, const int* in_sizes, int n_in,
                              void* d_out, int out_size) {
    const float* x  = nullptr;
    const float* W1 = nullptr;
    const float* W2 = nullptr;
    const void*  ei = nullptr;
    const void*  batch = nullptr;
    const float* v128[6] = {nullptr, nullptr, nullptr, nullptr, nullptr, nullptr};
    int n128 = 0;
    for (int i = 0; i < n_in; i++) {
        switch (in_sizes[i]) {
            case Nn * FIN:  x     = (const float*)d_in[i]; break;
            case 2 * Ee:    ei    = d_in[i];               break;
            case Nn:        batch = d_in[i];               break;
            case FIN * Hh:  W1    = (const float*)d_in[i]; break;
            case Hh * Hh:   W2    = (const float*)d_in[i]; break;
            case Hh:        if (n128 < 6) v128[n128++] = (const float*)d_in[i]; break;
        }
    }
    float* out = (float*)d_out;

    k_classify<<<1, 128>>>(ei, batch, v128[0], v128[1], v128[2],
                           v128[3], v128[4], v128[5]);
    k_setup   <<<(Nn + 255) / 256, 256>>>(W2);

    k_deg     <<<(Ee + 255) / 256, 256>>>(ei, batch);
    k_scan1   <<<25, 512>>>();
    k_scan2   <<<1, 1>>>();
    k_scan3   <<<(Nn + 255) / 256, 256>>>();
    k_scatter <<<(Ee + 255) / 256, 256>>>(ei);

    // layer 1 (fused agg + GEMM + BN1 stats)
    k_l1      <<<(Nn + 63) / 64, 256>>>(x, W1);
    k_bncoef  <<<1, 128>>>(0);

    // layer 2
    k_gemm2h  <<<(Nn + 127) / 128, 256>>>();      // in-place h1 -> xw2 (fp16)
    k_agg2h   <<<(Nn + 63) / 64, 256>>>();        // h2 fp16 + BN2 stats fused
    k_bncoef  <<<1, 128>>>(1);

    // pooling
    k_bscan   <<<1, 1024>>>();
    k_pool    <<<Bb, 128>>>(out);
}

// round 17
// speedup vs baseline: 1.0583x; 1.0583x over previous
#include <cuda_runtime.h>
#include <cuda_fp16.h>
#include <math.h>

#define Nn  100000
#define Ee  1600000
#define Bb  4096
#define FIN 25
#define Hh  128
#define EPSf 1e-5f

// ---------------- scratch (static __device__ — allocation-free) ----------------
__device__ __align__(16) float  g_h [Nn * Hh];   // x' (fp32), later h2 (fp16)
__device__ __align__(16) __half g_xwh[Nn * Hh];  // h1 fp16, then (in-place) Z fp16
__device__ __align__(16) __half g_W2h[Hh * Hh];  // W2 transposed fp16: [n][k]
__device__ int    g_deg[Nn];
__device__ int    g_cursor[Nn];
__device__ float  g_dinv[Nn];
__device__ int    g_rowstart[Nn + 1];
__device__ int    g_csr_src[Ee];                 // src only (coef folded into rows)
__device__ float  g_bnsum[Hh];
__device__ float  g_bnsq [Hh];
__device__ float  g_bnA[Hh];
__device__ float  g_bnB[Hh];
__device__ int    g_bsum[64];
__device__ int    g_bcnt[Bb];
__device__ int    g_boff[Bb];

// runtime-resolved input handles
__device__ int    g_ei64;
__device__ int    g_batch64;
__device__ const float* gp_b[2];
__device__ const float* gp_g[2];
__device__ const float* gp_be[2];

__device__ __forceinline__ int ld_idx(const void* p, long long i, int is64) {
    return is64 ? (int)((const long long*)p)[i] : ((const int*)p)[i];
}

// ---------------- setup: zero scratch + convert W2 to fp16^T ----------------
__global__ void k_setup(const float* __restrict__ W2) {
    int i = blockIdx.x * blockDim.x + threadIdx.x;
    if (i < Nn) { g_deg[i] = 0; g_cursor[i] = 0; }
    if (i < Bb) g_bcnt[i] = 0;
    if (i < Hh) { g_bnsum[i] = 0.f; g_bnsq[i] = 0.f; }
    if (i < Hh * Hh) {              // i = k*128 + n
        int k = i >> 7, n = i & 127;
        g_W2h[n * Hh + k] = __float2half(W2[i]);
    }
}

// ---------------- detect index width + classify 128-vectors ----------------
__global__ void k_classify(const void* ei, const void* batch,
                           const float* c0, const float* c1, const float* c2,
                           const float* c3, const float* c4, const float* c5) {
    int t = threadIdx.x, lane = t & 31, w = t >> 5;
    if (t == 0) {
        const long long* p = (const long long*)ei;
        int ok = 1;
        for (int i = 0; i < 16; i++) { long long v = p[i]; if (v < 0 || v >= Nn) ok = 0; }
        g_ei64 = ok;
        const long long* q = (const long long*)batch;
        int ok2 = 1;
        for (int i = 0; i < 16; i++) { long long v = q[i]; if (v < 0 || v >= Bb) ok2 = 0; }
        g_batch64 = ok2;
    }
    const float* c[6] = {c0, c1, c2, c3, c4, c5};
    __shared__ float s_sum[4], s_abs[4];
    int nb = 0, ng = 0, nbe = 0;
    for (int j = 0; j < 6; j++) {
        float v = c[j][t];
        float s = v, a = fabsf(v);
        for (int o = 16; o > 0; o >>= 1) {
            s += __shfl_down_sync(0xffffffffu, s, o);
            a += __shfl_down_sync(0xffffffffu, a, o);
        }
        if (lane == 0) { s_sum[w] = s; s_abs[w] = a; }
        __syncthreads();
        if (t == 0) {
            float S = s_sum[0] + s_sum[1] + s_sum[2] + s_sum[3];
            float A = s_abs[0] + s_abs[1] + s_abs[2] + s_abs[3];
            if (A == 0.0f)      { if (nb  < 2) gp_b [nb++]  = c[j]; }
            else if (S > 64.0f) { if (ng  < 2) gp_g [ng++]  = c[j]; }
            else                { if (nbe < 2) gp_be[nbe++] = c[j]; }
        }
        __syncthreads();
    }
}

// -------- degree histogram (2 edges/thread, vector loads) + batch count -------
__global__ void k_deg(const void* __restrict__ ei, const void* __restrict__ batch) {
    int i = blockIdx.x * blockDim.x + threadIdx.x;
    int e0 = i * 2;
    if (e0 < Ee) {
        int d0, d1;
        if (g_ei64) {
            ulonglong2 d = *(const ulonglong2*)((const long long*)ei + Ee + e0);
            d0 = (int)d.x; d1 = (int)d.y;
        } else {
            int2 d = *(const int2*)((const int*)ei + Ee + e0);
            d0 = d.x; d1 = d.y;
        }
        atomicAdd(&g_deg[d0], 1);
        atomicAdd(&g_deg[d1], 1);
    }
    if (i < Nn) {
        int b = ld_idx(batch, i, g_batch64);
        atomicAdd(&g_bcnt[b], 1);
    }
}

// ---------------- exclusive scan of deg -> rowstart (+dinv fused) -------------
__global__ void k_scan1() {
    __shared__ int sh[512];
    int b = blockIdx.x, t = threadIdx.x;
    int base = b * 4096 + t * 8;
    int v[8]; int tot = 0;
#pragma unroll
    for (int i = 0; i < 8; i++) {
        int idx = base + i;
        v[i] = (idx < Nn) ? g_deg[idx] : 0;
        if (idx < Nn) g_dinv[idx] = rsqrtf((float)v[i] + 1.0f);
        tot += v[i];
    }
    sh[t] = tot; __syncthreads();
    for (int off = 1; off < 512; off <<= 1) {
        int x = (t >= off) ? sh[t - off] : 0;
        __syncthreads();
        sh[t] += x;
        __syncthreads();
    }
    int run = sh[t] - tot;
#pragma unroll
    for (int i = 0; i < 8; i++) {
        int idx = base + i;
        if (idx < Nn) g_rowstart[idx] = run;
        run += v[i];
    }
    if (t == 511) g_bsum[b] = sh[511];
}

__global__ void k_scan2() {
    int run = 0;
    for (int b = 0; b < 25; b++) { int t = g_bsum[b]; g_bsum[b] = run; run += t; }
    g_rowstart[Nn] = run;
}

__global__ void k_scan3() {
    int i = blockIdx.x * blockDim.x + threadIdx.x;
    if (i < Nn) g_rowstart[i] += g_bsum[i >> 12];
}

// ---------------- x' = dinv[row] * x  (into g_h, fp32) ----------------
__global__ void k_prescale(const float* __restrict__ x) {
    int i = blockIdx.x * blockDim.x + threadIdx.x;
    if (i < Nn * FIN) {
        int node = i / FIN;
        ((float*)g_h)[i] = x[i] * g_dinv[node];
    }
}

// ---------------- scatter: src-only CSR (2 edges/thread) ----------------
__global__ void k_scatter(const void* __restrict__ ei) {
    int e0 = (blockIdx.x * blockDim.x + threadIdx.x) * 2;
    if (e0 >= Ee) return;
    int s0, s1, d0, d1;
    if (g_ei64) {
        ulonglong2 s = *(const ulonglong2*)((const long long*)ei + e0);
        ulonglong2 d = *(const ulonglong2*)((const long long*)ei + Ee + e0);
        s0 = (int)s.x; s1 = (int)s.y; d0 = (int)d.x; d1 = (int)d.y;
    } else {
        int2 s = *(const int2*)((const int*)ei + e0);
        int2 d = *(const int2*)((const int*)ei + Ee + e0);
        s0 = s.x; s1 = s.y; d0 = d.x; d1 = d.y;
    }
    int p0 = g_rowstart[d0] + atomicAdd(&g_cursor[d0], 1);
    g_csr_src[p0] = s0;
    int p1 = g_rowstart[d1] + atomicAdd(&g_cursor[d1], 1);
    g_csr_src[p1] = s1;
}

// -- layer 1 FUSED: gather x' rows (pure sum) -> @W1 + b1 -> h1 fp16 + BN1 stats
__global__ void __launch_bounds__(256) k_l1(const float* __restrict__ W1) {
    __shared__ float W1s[FIN * Hh];
    __shared__ float s_sum[Hh], s_sq[Hh];
    int t = threadIdx.x, lane = t & 31;
    for (int i = t; i < FIN * Hh; i += 256) W1s[i] = W1[i];
    if (t < Hh) { s_sum[t] = 0.f; s_sq[t] = 0.f; }
    __syncthreads();

    const float* xp = (const float*)g_h;        // pre-scaled x'
    const float* b1 = gp_b[0];
    float4 bv = __ldg(&((const float4*)b1)[lane]);
    bool act = lane < FIN;
    int node0 = ((blockIdx.x * blockDim.x + t) >> 5) * 8;
    float ls0 = 0.f, ls1 = 0.f, ls2 = 0.f, ls3 = 0.f;
    float lq0 = 0.f, lq1 = 0.f, lq2 = 0.f, lq3 = 0.f;

    for (int ni = 0; ni < 8; ni++) {
        int node = node0 + ni;
        if (node >= Nn) break;
        int s = g_rowstart[node];
        int e = g_rowstart[node + 1];
        float acc = 0.f;
        int p = s;
        for (; p + 4 <= e; p += 4) {
            int r0 = __ldg(&g_csr_src[p]),     r1 = __ldg(&g_csr_src[p + 1]);
            int r2 = __ldg(&g_csr_src[p + 2]), r3 = __ldg(&g_csr_src[p + 3]);
            float v0 = act ? __ldg(&xp[r0 * FIN + lane]) : 0.f;
            float v1 = act ? __ldg(&xp[r1 * FIN + lane]) : 0.f;
            float v2 = act ? __ldg(&xp[r2 * FIN + lane]) : 0.f;
            float v3 = act ? __ldg(&xp[r3 * FIN + lane]) : 0.f;
            acc += (v0 + v1) + (v2 + v3);
        }
        for (; p < e; p++) {
            int r0 = __ldg(&g_csr_src[p]);
            acc += act ? __ldg(&xp[r0 * FIN + lane]) : 0.f;
        }
        float dd = g_dinv[node];
        acc += act ? __ldg(&xp[node * FIN + lane]) : 0.f;   // self: x'[node]
        acc *= dd;                                          // dinv[dst] factor

        float4 o = bv;
#pragma unroll
        for (int k = 0; k < FIN; k++) {
            float a = __shfl_sync(0xffffffffu, acc, k);
            float4 w = *(const float4*)&W1s[k * Hh + lane * 4];
            o.x = fmaf(a, w.x, o.x);
            o.y = fmaf(a, w.y, o.y);
            o.z = fmaf(a, w.z, o.z);
            o.w = fmaf(a, w.w, o.w);
        }
        __half2 h0 = __floats2half2_rn(o.x, o.y);
        __half2 h1 = __floats2half2_rn(o.z, o.w);
        uint2 pk;
        pk.x = *(const unsigned*)&h0;
        pk.y = *(const unsigned*)&h1;
        *(uint2*)&g_xwh[node * Hh + lane * 4] = pk;
        ls0 += o.x; lq0 = fmaf(o.x, o.x, lq0);
        ls1 += o.y; lq1 = fmaf(o.y, o.y, lq1);
        ls2 += o.z; lq2 = fmaf(o.z, o.z, lq2);
        ls3 += o.w; lq3 = fmaf(o.w, o.w, lq3);
    }
    atomicAdd(&s_sum[lane * 4 + 0], ls0); atomicAdd(&s_sq[lane * 4 + 0], lq0);
    atomicAdd(&s_sum[lane * 4 + 1], ls1); atomicAdd(&s_sq[lane * 4 + 1], lq1);
    atomicAdd(&s_sum[lane * 4 + 2], ls2); atomicAdd(&s_sq[lane * 4 + 2], lq2);
    atomicAdd(&s_sum[lane * 4 + 3], ls3); atomicAdd(&s_sq[lane * 4 + 3], lq3);
    __syncthreads();
    if (t < Hh) {
        atomicAdd(&g_bnsum[t], s_sum[t]);
        atomicAdd(&g_bnsq [t], s_sq[t]);
    }
}

__global__ void k_bncoef(int layer) {
    int c = threadIdx.x;
    const float* gam = gp_g[layer];
    const float* bet = gp_be[layer];
    double m   = (double)g_bnsum[c] / (double)Nn;
    double var = (double)g_bnsq[c] / (double)Nn - m * m;
    float  A   = (float)((double)gam[c] / sqrt(var + (double)EPSf));
    g_bnA[c] = A;
    g_bnB[c] = bet[c] - (float)m * A;
    g_bnsum[c] = 0.f; g_bnsq[c] = 0.f;
}

// -- GEMM2 (HMMA): relu(bn(h1)) @ W2, output pre-scaled by dinv -> Z (in-place) -
__global__ void __launch_bounds__(256) k_gemm2h() {
    __shared__ __half As[128][72];
    __shared__ __half Bs[128][72];
    __shared__ float  sA[Hh], sB[Hh];
    int t    = threadIdx.x;
    int warp = t >> 5, lane = t & 31;
    int grp  = lane >> 2, thr = lane & 3;
    int row0 = blockIdx.x * 128;
    if (t < 128) { sA[t] = g_bnA[t]; sB[t] = g_bnB[t]; }
    __syncthreads();

    float acc[16][4];
#pragma unroll
    for (int n = 0; n < 16; n++)
#pragma unroll
        for (int j = 0; j < 4; j++) acc[n][j] = 0.f;

    for (int ko = 0; ko < Hh; ko += 64) {
        {
            int r  = t >> 1;
            int c0 = (t & 1) * 32;
            int row = row0 + r;
#pragma unroll
            for (int j = 0; j < 8; j++) {
                int col = ko + c0 + j * 4;
                float2 f0 = make_float2(0.f, 0.f), f1 = make_float2(0.f, 0.f);
                if (row < Nn) {
                    uint2 raw = *(const uint2*)&g_xwh[row * Hh + col];
                    f0 = __half22float2(*(const __half2*)&raw.x);
                    f1 = __half22float2(*(const __half2*)&raw.y);
                    f0.x = fmaxf(fmaf(f0.x, sA[col + 0], sB[col + 0]), 0.f);
                    f0.y = fmaxf(fmaf(f0.y, sA[col + 1], sB[col + 1]), 0.f);
                    f1.x = fmaxf(fmaf(f1.x, sA[col + 2], sB[col + 2]), 0.f);
                    f1.y = fmaxf(fmaf(f1.y, sA[col + 3], sB[col + 3]), 0.f);
                }
                *(__half2*)&As[r][c0 + j * 4]     = __floats2half2_rn(f0.x, f0.y);
                *(__half2*)&As[r][c0 + j * 4 + 2] = __floats2half2_rn(f1.x, f1.y);
            }
        }
        {
            int n  = t >> 1;
            int c0 = (t & 1) * 32;
#pragma unroll
            for (int j = 0; j < 4; j++) {
                uint4 w = *(const uint4*)&g_W2h[n * Hh + ko + c0 + j * 8];
                *(uint4*)&Bs[n][c0 + j * 8] = w;
            }
        }
        __syncthreads();
#pragma unroll
        for (int kc = 0; kc < 4; kc++) {
            int kb = kc * 16;
            unsigned a0 = *(const unsigned*)&As[warp * 16 + grp    ][kb + thr * 2];
            unsigned a1 = *(const unsigned*)&As[warp * 16 + grp + 8][kb + thr * 2];
            unsigned a2 = *(const unsigned*)&As[warp * 16 + grp    ][kb + thr * 2 + 8];
            unsigned a3 = *(const unsigned*)&As[warp * 16 + grp + 8][kb + thr * 2 + 8];
#pragma unroll
            for (int n = 0; n < 16; n++) {
                unsigned b0 = *(const unsigned*)&Bs[n * 8 + grp][kb + thr * 2];
                unsigned b1 = *(const unsigned*)&Bs[n * 8 + grp][kb + thr * 2 + 8];
                asm volatile(
                    "mma.sync.aligned.m16n8k16.row.col.f32.f16.f16.f32 "
                    "{%0,%1,%2,%3}, {%4,%5,%6,%7}, {%8,%9}, {%0,%1,%2,%3};"
                    : "+f"(acc[n][0]), "+f"(acc[n][1]), "+f"(acc[n][2]), "+f"(acc[n][3])
                    : "r"(a0), "r"(a1), "r"(a2), "r"(a3), "r"(b0), "r"(b1));
            }
        }
        __syncthreads();
    }
    int rA = row0 + warp * 16 + grp;
    int rB = rA + 8;
    float dA = (rA < Nn) ? g_dinv[rA] : 0.f;    // fold dinv[row] into Z
    float dB = (rB < Nn) ? g_dinv[rB] : 0.f;
#pragma unroll
    for (int n = 0; n < 16; n++) {
        int col = n * 8 + thr * 2;
        if (rA < Nn) *(__half2*)&g_xwh[rA * Hh + col] = __floats2half2_rn(acc[n][0] * dA, acc[n][1] * dA);
        if (rB < Nn) *(__half2*)&g_xwh[rB * Hh + col] = __floats2half2_rn(acc[n][2] * dB, acc[n][3] * dB);
    }
}

// -- layer-2 aggregation: pure row sum of Z, final dinv scale, BN2 stats -------
__global__ void __launch_bounds__(256) k_agg2h() {
    __shared__ float s_sum[Hh], s_sq[Hh];
    int t = threadIdx.x;
    if (t < Hh) { s_sum[t] = 0.f; s_sq[t] = 0.f; }
    __syncthreads();
    int lane = t & 31;
    int node0 = ((blockIdx.x * blockDim.x + t) >> 5) * 8;
    const float* bias = gp_b[1];
    float4 bv = __ldg(&((const float4*)bias)[lane]);
    const uint2* zt = (const uint2*)g_xwh;
    __half* h2 = (__half*)g_h;
    float ls0 = 0.f, ls1 = 0.f, ls2 = 0.f, ls3 = 0.f;
    float lq0 = 0.f, lq1 = 0.f, lq2 = 0.f, lq3 = 0.f;

    for (int ni = 0; ni < 8; ni++) {
        int node = node0 + ni;
        if (node >= Nn) break;
        int s = g_rowstart[node];
        int e = g_rowstart[node + 1];
        float4 acc = make_float4(0.f, 0.f, 0.f, 0.f);
        int p = s;
        for (; p + 4 <= e; p += 4) {
            int r0 = __ldg(&g_csr_src[p]),     r1 = __ldg(&g_csr_src[p + 1]);
            int r2 = __ldg(&g_csr_src[p + 2]), r3 = __ldg(&g_csr_src[p + 3]);
            uint2 w0 = __ldg(&zt[r0 * 32 + lane]);
            uint2 w1 = __ldg(&zt[r1 * 32 + lane]);
            uint2 w2 = __ldg(&zt[r2 * 32 + lane]);
            uint2 w3 = __ldg(&zt[r3 * 32 + lane]);
            float2 p0, p1;
            p0 = __half22float2(*(const __half2*)&w0.x); p1 = __half22float2(*(const __half2*)&w0.y);
            acc.x += p0.x; acc.y += p0.y; acc.z += p1.x; acc.w += p1.y;
            p0 = __half22float2(*(const __half2*)&w1.x); p1 = __half22float2(*(const __half2*)&w1.y);
            acc.x += p0.x; acc.y += p0.y; acc.z += p1.x; acc.w += p1.y;
            p0 = __half22float2(*(const __half2*)&w2.x); p1 = __half22float2(*(const __half2*)&w2.y);
            acc.x += p0.x; acc.y += p0.y; acc.z += p1.x; acc.w += p1.y;
            p0 = __half22float2(*(const __half2*)&w3.x); p1 = __half22float2(*(const __half2*)&w3.y);
            acc.x += p0.x; acc.y += p0.y; acc.z += p1.x; acc.w += p1.y;
        }
        for (; p < e; p++) {
            int r0 = __ldg(&g_csr_src[p]);
            uint2 w0 = __ldg(&zt[r0 * 32 + lane]);
            float2 p0 = __half22float2(*(const __half2*)&w0.x);
            float2 p1 = __half22float2(*(const __half2*)&w0.y);
            acc.x += p0.x; acc.y += p0.y; acc.z += p1.x; acc.w += p1.y;
        }
        // self term: + Z[node], then scale by dinv[node], add bias
        uint2 wr = zt[node * 32 + lane];
        float2 f0 = __half22float2(*(const __half2*)&wr.x);
        float2 f1 = __half22float2(*(const __half2*)&wr.y);
        float dd = g_dinv[node];
        acc.x = fmaf(acc.x + f0.x, dd, bv.x);
        acc.y = fmaf(acc.y + f0.y, dd, bv.y);
        acc.z = fmaf(acc.z + f1.x, dd, bv.z);
        acc.w = fmaf(acc.w + f1.y, dd, bv.w);
        __half2 o0 = __floats2half2_rn(acc.x, acc.y);
        __half2 o1 = __floats2half2_rn(acc.z, acc.w);
        uint2 pk;
        pk.x = *(const unsigned*)&o0;
        pk.y = *(const unsigned*)&o1;
        *(uint2*)&h2[node * Hh + lane * 4] = pk;
        ls0 += acc.x; lq0 = fmaf(acc.x, acc.x, lq0);
        ls1 += acc.y; lq1 = fmaf(acc.y, acc.y, lq1);
        ls2 += acc.z; lq2 = fmaf(acc.z, acc.z, lq2);
        ls3 += acc.w; lq3 = fmaf(acc.w, acc.w, lq3);
    }
    atomicAdd(&s_sum[lane * 4 + 0], ls0); atomicAdd(&s_sq[lane * 4 + 0], lq0);
    atomicAdd(&s_sum[lane * 4 + 1], ls1); atomicAdd(&s_sq[lane * 4 + 1], lq1);
    atomicAdd(&s_sum[lane * 4 + 2], ls2); atomicAdd(&s_sq[lane * 4 + 2], lq2);
    atomicAdd(&s_sum[lane * 4 + 3], ls3); atomicAdd(&s_sq[lane * 4 + 3], lq3);
    __syncthreads();
    if (t < Hh) {
        atomicAdd(&g_bnsum[t], s_sum[t]);
        atomicAdd(&g_bnsq [t], s_sq[t]);
    }
}

// ---------------- batch pooling ----------------
__global__ void k_bscan() {
    __shared__ int sh[1024];
    int t = threadIdx.x;
    int base = t * 4;
    int v[4]; int tot = 0;
#pragma unroll
    for (int i = 0; i < 4; i++) { v[i] = g_bcnt[base + i]; tot += v[i]; }
    sh[t] = tot; __syncthreads();
    for (int off = 1; off < 1024; off <<= 1) {
        int x = (t >= off) ? sh[t - off] : 0;
        __syncthreads();
        sh[t] += x;
        __syncthreads();
    }
    int run = sh[t] - tot;
#pragma unroll
    for (int i = 0; i < 4; i++) { g_boff[base + i] = run; run += v[i]; }
}

__global__ void k_pool(float* __restrict__ out) {
    int g = blockIdx.x;
    int c = threadIdx.x;
    int st = g_boff[g], cn = g_bcnt[g];
    const __half* h2 = (const __half*)g_h;
    float A = g_bnA[c], Bc = g_bnB[c];
    float s = 0.f, mx = -INFINITY;
    for (int r = st; r < st + cn; r++) {
        float v = __half2float(h2[r * Hh + c]);
        v = fmaxf(fmaf(v, A, Bc), 0.f);
        s += v;
        mx = fmaxf(mx, v);
    }
    out[g * 384 + c]       = s / (float)max(cn, 1);
    out[g * 384 + 128 + c] = (cn > 0) ? mx : 0.f;
    out[g * 384 + 256 + c] = s;
}

// ---------------- launch ----------------
extern "C" void kernel_launch(void* const* d_in, const int* in_sizes, int n_in,
                              void* d_out, int out_size) {
    const float* x  = nullptr;
    const float* W1 = nullptr;
    const float* W2 = nullptr;
    const void*  ei = nullptr;
    const void*  batch = nullptr;
    const float* v128[6] = {nullptr, nullptr, nullptr, nullptr, nullptr, nullptr};
    int n128 = 0;
    for (int i = 0; i < n_in; i++) {
        switch (in_sizes[i]) {
            case Nn * FIN:  x     = (const float*)d_in[i]; break;
            case 2 * Ee:    ei    = d_in[i];               break;
            case Nn:        batch = d_in[i];               break;
            case FIN * Hh:  W1    = (const float*)d_in[i]; break;
            case Hh * Hh:   W2    = (const float*)d_in[i]; break;
            case Hh:        if (n128 < 6) v128[n128++] = (const float*)d_in[i]; break;
        }
    }
    float* out = (float*)d_out;

    k_classify<<<1, 128>>>(ei, batch, v128[0], v128[1], v128[2],
                           v128[3], v128[4], v128[5]);
    k_setup   <<<(Nn + 255) / 256, 256>>>(W2);

    k_deg     <<<(Ee / 2 + 255) / 256, 256>>>(ei, batch);
    k_scan1   <<<25, 512>>>();
    k_scan2   <<<1, 1>>>();
    k_scan3   <<<(Nn + 255) / 256, 256>>>();
    k_prescale<<<(Nn * FIN + 255) / 256, 256>>>(x);
    k_scatter <<<(Ee / 2 + 255) / 256, 256>>>(ei);

    // layer 1 (fused gather + GEMM + BN1 stats)
    k_l1      <<<(Nn + 63) / 64, 256>>>(W1);
    k_bncoef  <<<1, 128>>>(0);

    // layer 2
    k_gemm2h  <<<(Nn + 127) / 128, 256>>>();      // in-place h1 -> Z (dinv-scaled)
    k_agg2h   <<<(Nn + 63) / 64, 256>>>();        // pure-sum gather + BN2 stats
    k_bncoef  <<<1, 128>>>(1);

    // pooling
    k_bscan   <<<1, 1024>>>();
    k_pool    <<<Bb, 128>>>(out);
}